// round 3
// baseline (speedup 1.0000x reference)
#include <cuda_runtime.h>

// ---------------------------------------------------------------------------
// Swin shifted-window attention block, fp32 baseline.
//   K1: W_comb = w_out @ w_post          (384x384x384)
//   K2: b_comb = b_out @ w_post + b_post
//   K3: qkv = roll(x,-3,-3) @ w_qkv, scattered to per-window layout, q scaled
//   K4: per-(b,head,window) attention (bias gather + shift masks + softmax)
//   K5: out = attn @ W_comb + b_comb, scattered with roll(+3,+3) into d_out
// ---------------------------------------------------------------------------

#define BATCH 16
#define HW    56
#define DIM   384
#define NHEAD 12
#define HDIM  32
#define WSZ   7
#define NWIN  64          // 8x8 windows
#define TOK   49
#define M_TOK (BATCH*HW*HW)            // 50176
#define QKV_N (3*NHEAD*HDIM)           // 1152
#define SZ1   (BATCH*NHEAD*NWIN*TOK*HDIM) // 19,267,584 floats per q/k/v

__device__ float g_qkv[3u * SZ1];          // q|k|v windowed scratch (~231 MB)
__device__ float g_attn[(size_t)M_TOK * DIM]; // attention output (~77 MB)
__device__ float g_Wc[DIM * DIM];
__device__ float g_bc[DIM];

#define MODE_COMB 0
#define MODE_QKV  1
#define MODE_PROJ 2

// 128x128x8 SGEMM, 256 threads, 8x8 micro-tile. All K == 384 here.
template <int MODE>
__global__ __launch_bounds__(256, 2)
void sgemm128(const float* __restrict__ Aex,
              const float* __restrict__ Bex,
              float* __restrict__ Cex,
              int M, int N, int K)
{
    const float* A = (MODE == MODE_PROJ) ? g_attn : Aex;
    const float* B = (MODE == MODE_PROJ) ? g_Wc  : Bex;

    __shared__ float As[8][128];
    __shared__ float Bs[8][128];
    __shared__ int aOff[128];
    __shared__ int cBase[128];

    const int tid = threadIdx.x;
    const int m0 = blockIdx.y * 128;
    const int n0 = blockIdx.x * 128;

    if (tid < 128) {
        int m = m0 + tid;
        if (MODE == MODE_COMB) {
            aOff[tid]  = m * 384;
            cBase[tid] = m * N;
        } else {
            int b = m / 3136;
            int t = m - b * 3136;
            int hh = t / 56, ww = t - (t / 56) * 56;
            if (MODE == MODE_QKV) {
                int sh = hh + 3; if (sh >= 56) sh -= 56;   // roll(-3)
                int sw = ww + 3; if (sw >= 56) sw -= 56;
                aOff[tid] = ((b * 56 + sh) * 56 + sw) * 384;
                int wy = hh / 7, xi = hh - wy * 7;
                int wx = ww / 7, yi = ww - wx * 7;
                // base for (b, h=0, win, tok); add h*64*1568 at store time
                cBase[tid] = (b * 768 + wy * 8 + wx) * 1568 + (xi * 7 + yi) * 32;
            } else { // PROJ
                aOff[tid] = m * 384;
                int dh = hh + 3; if (dh >= 56) dh -= 56;   // roll(+3): shifted row -> out row
                int dw = ww + 3; if (dw >= 56) dw -= 56;
                cBase[tid] = ((b * 56 + dh) * 56 + dw) * 384;
            }
        }
    }
    __syncthreads();

    const int aRow = tid >> 1;
    const int aK4  = (tid & 1) * 4;
    const int bRow = tid >> 5;
    const int bC4  = (tid & 31) * 4;
    const int tr8  = (tid >> 4) * 8;
    const int tc8  = (tid & 15) * 8;

    float acc[8][8];
#pragma unroll
    for (int i = 0; i < 8; i++)
#pragma unroll
        for (int j = 0; j < 8; j++) acc[i][j] = 0.f;

    const float* aPtr = A + aOff[aRow] + aK4;
    const float* bPtr = B + bRow * N + n0 + bC4;

    float4 av = *(const float4*)aPtr;
    float4 bv = *(const float4*)bPtr;

    for (int k0 = 0; k0 < K; k0 += 8) {
        As[aK4 + 0][aRow] = av.x;
        As[aK4 + 1][aRow] = av.y;
        As[aK4 + 2][aRow] = av.z;
        As[aK4 + 3][aRow] = av.w;
        *(float4*)&Bs[bRow][bC4] = bv;
        __syncthreads();

        if (k0 + 8 < K) {
            av = *(const float4*)(aPtr + k0 + 8);
            bv = *(const float4*)(bPtr + (size_t)(k0 + 8) * N);
        }

#pragma unroll
        for (int kk = 0; kk < 8; kk++) {
            float ar[8], br[8];
            *(float4*)&ar[0] = *(const float4*)&As[kk][tr8];
            *(float4*)&ar[4] = *(const float4*)&As[kk][tr8 + 4];
            *(float4*)&br[0] = *(const float4*)&Bs[kk][tc8];
            *(float4*)&br[4] = *(const float4*)&Bs[kk][tc8 + 4];
#pragma unroll
            for (int i = 0; i < 8; i++)
#pragma unroll
                for (int j = 0; j < 8; j++)
                    acc[i][j] += ar[i] * br[j];
        }
        __syncthreads();
    }

    // ---- epilogue ----
    if (MODE == MODE_QKV) {
        int n   = n0 + tc8;
        int s   = n / 384;
        int rem = n - s * 384;
        int h   = rem >> 5;
        int d0  = rem & 31;   // 8 cols never cross a head (32 % 8 == 0)
        float scale = (s == 0) ? 0.17677669529663687f : 1.0f; // 1/sqrt(32) on q
        float* base = g_qkv + (size_t)s * SZ1 + h * 100352 + d0; // 100352 = 64*1568
#pragma unroll
        for (int i = 0; i < 8; i++) {
            float* p = base + cBase[tr8 + i];
            float4 v0 = make_float4(acc[i][0]*scale, acc[i][1]*scale, acc[i][2]*scale, acc[i][3]*scale);
            float4 v1 = make_float4(acc[i][4]*scale, acc[i][5]*scale, acc[i][6]*scale, acc[i][7]*scale);
            *(float4*)p       = v0;
            *(float4*)(p + 4) = v1;
        }
    } else if (MODE == MODE_PROJ) {
        float bb[8];
#pragma unroll
        for (int j = 0; j < 8; j++) bb[j] = g_bc[n0 + tc8 + j];
#pragma unroll
        for (int i = 0; i < 8; i++) {
            float* p = Cex + cBase[tr8 + i] + n0 + tc8;
            float4 v0 = make_float4(acc[i][0]+bb[0], acc[i][1]+bb[1], acc[i][2]+bb[2], acc[i][3]+bb[3]);
            float4 v1 = make_float4(acc[i][4]+bb[4], acc[i][5]+bb[5], acc[i][6]+bb[6], acc[i][7]+bb[7]);
            *(float4*)p       = v0;
            *(float4*)(p + 4) = v1;
        }
    } else { // COMB -> g_Wc
#pragma unroll
        for (int i = 0; i < 8; i++) {
            float* p = g_Wc + cBase[tr8 + i] + n0 + tc8;
            float4 v0 = make_float4(acc[i][0], acc[i][1], acc[i][2], acc[i][3]);
            float4 v1 = make_float4(acc[i][4], acc[i][5], acc[i][6], acc[i][7]);
            *(float4*)p       = v0;
            *(float4*)(p + 4) = v1;
        }
    }
}

__global__ void bias_comb_kernel(const float* __restrict__ b_out,
                                 const float* __restrict__ w_post,
                                 const float* __restrict__ b_post)
{
    int j = blockIdx.x * blockDim.x + threadIdx.x;
    if (j < 384) {
        float s = b_post[j];
        for (int k = 0; k < 384; k++) s += b_out[k] * w_post[k * 384 + j];
        g_bc[j] = s;
    }
}

// One block per (b, head, window). 8 warps; each warp owns score-rows i, i+8, ...
__global__ __launch_bounds__(256)
void attn_kernel(const float* __restrict__ pe)
{
    __shared__ float qs[49 * 33];
    __shared__ float ks[49 * 33];
    __shared__ float vs[49 * 33];
    __shared__ float pes[169];
    __shared__ float ps[8][52];

    const int tid = threadIdx.x;
    const int bw  = blockIdx.x;          // (b*12 + h)*64 + win
    const int win = bw & 63;
    const int bh  = bw >> 6;
    const int h   = bh % 12;
    const int b   = bh / 12;
    const size_t base = (size_t)bw * 1568;

    for (int idx = tid; idx < 1568; idx += 256) {
        int r = idx >> 5, c = idx & 31;
        qs[r * 33 + c] = g_qkv[base + idx];
        ks[r * 33 + c] = g_qkv[(size_t)SZ1 + base + idx];
        vs[r * 33 + c] = g_qkv[2u * (size_t)SZ1 + base + idx];
    }
    if (tid < 169) pes[tid] = pe[tid];
    __syncthreads();

    const bool mUL = (win >= 56);        // wy == 7
    const bool mLR = ((win & 7) == 7);   // wx == 7
    const int warp = tid >> 5, lane = tid & 31;
    const int j0 = lane;
    const int j1 = lane + 32;
    const bool j1v = (j1 < 49);
    const int j1c = j1v ? j1 : 48;
    const int xj0 = j0 / 7,  yj0 = j0  - xj0 * 7;
    const int xj1 = j1c / 7, yj1 = j1c - xj1 * 7;
    const int wy = win >> 3, wx = win & 7;

    for (int i = warp; i < 49; i += 8) {
        const int xi = i / 7, yi = i - xi * 7;
        const float* qrow = qs + i * 33;
        const float* k0r  = ks + j0  * 33;
        const float* k1r  = ks + j1c * 33;
        float s0 = 0.f, s1 = 0.f;
#pragma unroll
        for (int d = 0; d < 32; d++) {
            float qv = qrow[d];
            s0 += qv * k0r[d];
            s1 += qv * k1r[d];
        }
        // relative position bias: pe[(xj - xi + 6), (yj - yi + 6)]
        s0 += pes[(xj0 - xi + 6) * 13 + (yj0 - yi + 6)];
        s1 += pes[(xj1 - xi + 6) * 13 + (yj1 - yi + 6)];
        if (mUL) {
            if ((i >= 28) != (j0  >= 28)) s0 = -1e30f;
            if ((i >= 28) != (j1c >= 28)) s1 = -1e30f;
        }
        if (mLR) {
            if ((yi >= 4) != (yj0 >= 4)) s0 = -1e30f;
            if ((yi >= 4) != (yj1 >= 4)) s1 = -1e30f;
        }
        if (!j1v) s1 = -1e30f;

        float mx = fmaxf(s0, s1);
#pragma unroll
        for (int o = 16; o > 0; o >>= 1)
            mx = fmaxf(mx, __shfl_xor_sync(0xffffffffu, mx, o));
        float e0 = __expf(s0 - mx);
        float e1 = j1v ? __expf(s1 - mx) : 0.f;
        float sum = e0 + e1;
#pragma unroll
        for (int o = 16; o > 0; o >>= 1)
            sum += __shfl_xor_sync(0xffffffffu, sum, o);
        float inv = 1.0f / sum;
        ps[warp][j0] = e0 * inv;
        if (j1v) ps[warp][j1] = e1 * inv;
        __syncwarp();

        float acc = 0.f;
#pragma unroll
        for (int j = 0; j < 49; j++)
            acc += ps[warp][j] * vs[j * 33 + lane];

        // merge windows (still in shifted coordinates)
        int hh = wy * 7 + xi, ww = wx * 7 + yi;
        size_t m = (size_t)(b * 56 + hh) * 56 + ww;
        g_attn[m * 384 + h * 32 + lane] = acc;
        __syncwarp();
    }
}

extern "C" void kernel_launch(void* const* d_in, const int* in_sizes, int n_in,
                              void* d_out, int out_size)
{
    const float* x     = (const float*)d_in[0];
    const float* wqkv  = (const float*)d_in[1];
    const float* pe    = (const float*)d_in[2];
    const float* wout  = (const float*)d_in[3];
    const float* bout  = (const float*)d_in[4];
    const float* wpost = (const float*)d_in[5];
    const float* bpost = (const float*)d_in[6];
    float* out = (float*)d_out;

    (void)in_sizes; (void)n_in; (void)out_size;

    // fold the two output projections into one
    sgemm128<MODE_COMB><<<dim3(3, 3), 256>>>(wout, wpost, nullptr, 384, 384, 384);
    bias_comb_kernel<<<2, 192>>>(bout, wpost, bpost);

    // shifted QKV projection -> windowed scratch
    sgemm128<MODE_QKV><<<dim3(QKV_N / 128, M_TOK / 128), 256>>>(
        x, wqkv, nullptr, M_TOK, QKV_N, 384);

    // windowed attention
    attn_kernel<<<BATCH * NHEAD * NWIN, 256>>>(pe);

    // fused projection + bias + roll(+3,+3) -> d_out
    sgemm128<MODE_PROJ><<<dim3(DIM / 128, M_TOK / 128), 256>>>(
        nullptr, nullptr, out, M_TOK, DIM, 384);
}

// round 7
// speedup vs baseline: 2.9104x; 2.9104x over previous
#include <cuda_runtime.h>

// ---------------------------------------------------------------------------
// Swin shifted-window attention block.
//   K1: W_comb = w_out @ w_post  (tf32 mma)
//   K2: b_comb = b_out @ w_post + b_post
//   K3: qkv = roll(x,-3,-3) @ w_qkv  (tf32 mma), scattered windowed, q scaled
//   K4: per-(b,head,window) attention, fp32 (vectorized smem access)
//   K5: out = attn @ W_comb + b_comb (tf32 mma), scatter roll(+3,+3)
// ---------------------------------------------------------------------------

#define BATCH 16
#define HW    56
#define DIM   384
#define NHEAD 12
#define HDIM  32
#define NWIN  64
#define M_TOK (BATCH*HW*HW)            // 50176
#define QKV_N (3*NHEAD*HDIM)           // 1152
#define SZ1   (BATCH*NHEAD*NWIN*49*HDIM) // 19,267,584 per q/k/v

__device__ float g_qkv[3u * SZ1];
__device__ float g_attn[(size_t)M_TOK * DIM];
__device__ float g_Wc[DIM * DIM];
__device__ float g_bc[DIM];

#define MODE_COMB 0
#define MODE_QKV  1
#define MODE_PROJ 2

__device__ __forceinline__ float f2tf(float x) {
    unsigned r;
    asm("cvt.rna.tf32.f32 %0, %1;" : "=r"(r) : "f"(x));
    return __uint_as_float(r);
}

__device__ __forceinline__ void mma_tf32(float* c, const float* a, const float* b) {
    asm volatile(
        "mma.sync.aligned.m16n8k8.row.col.f32.tf32.tf32.f32 "
        "{%0,%1,%2,%3}, {%4,%5,%6,%7}, {%8,%9}, {%0,%1,%2,%3};\n"
        : "+f"(c[0]), "+f"(c[1]), "+f"(c[2]), "+f"(c[3])
        : "r"(__float_as_uint(a[0])), "r"(__float_as_uint(a[1])),
          "r"(__float_as_uint(a[2])), "r"(__float_as_uint(a[3])),
          "r"(__float_as_uint(b[0])), "r"(__float_as_uint(b[1])));
}

// 128x128 block tile, warp tile 64x32 (warpM 0..1, warpN 0..3), K-chunk 16,
// double-buffered shared. K == 384 always.
template <int MODE>
__global__ __launch_bounds__(256)
void tf32gemm(const float* __restrict__ Aex,
              const float* __restrict__ Bex,
              float* __restrict__ Cex,
              int M, int N, int K)
{
    const float* A = (MODE == MODE_PROJ) ? g_attn : Aex;
    const float* B = (MODE == MODE_PROJ) ? g_Wc  : Bex;

    __shared__ __align__(16) float As[2][128][20];
    __shared__ __align__(16) float Bs[2][16][136];
    __shared__ int aOffS[128];
    __shared__ int cBase[128];

    const int tid = threadIdx.x;
    const int m0  = blockIdx.y * 128;
    const int n0  = blockIdx.x * 128;

    if (tid < 128) {
        int m = m0 + tid;
        if (MODE == MODE_COMB) {
            aOffS[tid] = m * 384;
            cBase[tid] = m * N;
        } else {
            int b = m / 3136;
            int t = m - b * 3136;
            int hh = t / 56, ww = t - (t / 56) * 56;
            if (MODE == MODE_QKV) {
                int sh = hh + 3; if (sh >= 56) sh -= 56;   // roll(-3)
                int sw = ww + 3; if (sw >= 56) sw -= 56;
                aOffS[tid] = ((b * 56 + sh) * 56 + sw) * 384;
                int wy = hh / 7, xi = hh - wy * 7;
                int wx = ww / 7, yi = ww - wx * 7;
                cBase[tid] = (b * 768 + wy * 8 + wx) * 1568 + (xi * 7 + yi) * 32;
            } else {
                aOffS[tid] = m * 384;
                int dh = hh + 3; if (dh >= 56) dh -= 56;   // roll(+3)
                int dw = ww + 3; if (dw >= 56) dw -= 56;
                cBase[tid] = ((b * 56 + dh) * 56 + dw) * 384;
            }
        }
    }
    __syncthreads();

    const int aRow = tid >> 1, aCol = (tid & 1) * 8;
    const int bRow = tid >> 4, bCol = (tid & 15) * 8;
    const int lane = tid & 31, grp = lane >> 2, qk = lane & 3;
    const int warpId = tid >> 5;
    const int warpM = warpId & 1;     // *64
    const int warpN = warpId >> 1;    // *32

    const float* aPtr = A + aOffS[aRow] + aCol;
    const float* bPtr = B + (size_t)bRow * N + n0 + bCol;

    float acc[4][4][4];
#pragma unroll
    for (int i = 0; i < 4; i++)
#pragma unroll
        for (int j = 0; j < 4; j++)
#pragma unroll
            for (int r = 0; r < 4; r++) acc[i][j][r] = 0.f;

    float4 ra0 = *(const float4*)(aPtr);
    float4 ra1 = *(const float4*)(aPtr + 4);
    float4 rb0 = *(const float4*)(bPtr);
    float4 rb1 = *(const float4*)(bPtr + 4);

    // stage chunk 0 -> buf 0
    {
        float* d = &As[0][aRow][aCol];
        d[0]=f2tf(ra0.x); d[1]=f2tf(ra0.y); d[2]=f2tf(ra0.z); d[3]=f2tf(ra0.w);
        d[4]=f2tf(ra1.x); d[5]=f2tf(ra1.y); d[6]=f2tf(ra1.z); d[7]=f2tf(ra1.w);
        float* e = &Bs[0][bRow][bCol];
        e[0]=f2tf(rb0.x); e[1]=f2tf(rb0.y); e[2]=f2tf(rb0.z); e[3]=f2tf(rb0.w);
        e[4]=f2tf(rb1.x); e[5]=f2tf(rb1.y); e[6]=f2tf(rb1.z); e[7]=f2tf(rb1.w);
    }
    __syncthreads();

    const int NK = 384 / 16;  // 24
    int buf = 0;
    for (int kc = 0; kc < NK; kc++) {
        if (kc + 1 < NK) {
            const float* ap = aPtr + (kc + 1) * 16;
            const float* bp = bPtr + (size_t)(kc + 1) * 16 * N;
            ra0 = *(const float4*)(ap);
            ra1 = *(const float4*)(ap + 4);
            rb0 = *(const float4*)(bp);
            rb1 = *(const float4*)(bp + 4);
        }

#pragma unroll
        for (int s = 0; s < 16; s += 8) {
            float af[4][4], bf[4][2];
#pragma unroll
            for (int mi = 0; mi < 4; mi++) {
                int r = warpM * 64 + mi * 16 + grp;
                af[mi][0] = As[buf][r][s + qk];
                af[mi][1] = As[buf][r + 8][s + qk];
                af[mi][2] = As[buf][r][s + qk + 4];
                af[mi][3] = As[buf][r + 8][s + qk + 4];
            }
#pragma unroll
            for (int ni = 0; ni < 4; ni++) {
                int c = warpN * 32 + ni * 8 + grp;
                bf[ni][0] = Bs[buf][s + qk][c];
                bf[ni][1] = Bs[buf][s + qk + 4][c];
            }
#pragma unroll
            for (int mi = 0; mi < 4; mi++)
#pragma unroll
                for (int ni = 0; ni < 4; ni++)
                    mma_tf32(acc[mi][ni], af[mi], bf[ni]);
        }

        if (kc + 1 < NK) {
            int nb = buf ^ 1;
            float* d = &As[nb][aRow][aCol];
            d[0]=f2tf(ra0.x); d[1]=f2tf(ra0.y); d[2]=f2tf(ra0.z); d[3]=f2tf(ra0.w);
            d[4]=f2tf(ra1.x); d[5]=f2tf(ra1.y); d[6]=f2tf(ra1.z); d[7]=f2tf(ra1.w);
            float* e = &Bs[nb][bRow][bCol];
            e[0]=f2tf(rb0.x); e[1]=f2tf(rb0.y); e[2]=f2tf(rb0.z); e[3]=f2tf(rb0.w);
            e[4]=f2tf(rb1.x); e[5]=f2tf(rb1.y); e[6]=f2tf(rb1.z); e[7]=f2tf(rb1.w);
        }
        __syncthreads();
        buf ^= 1;
    }

    // ---- epilogue ----
#pragma unroll
    for (int mi = 0; mi < 4; mi++) {
        int r0r = warpM * 64 + mi * 16 + grp;
#pragma unroll
        for (int half = 0; half < 2; half++) {
            int r = r0r + half * 8;
#pragma unroll
            for (int ni = 0; ni < 4; ni++) {
                int cc = warpN * 32 + ni * 8 + qk * 2;
                float c0 = acc[mi][ni][half * 2 + 0];
                float c1 = acc[mi][ni][half * 2 + 1];
                if (MODE == MODE_QKV) {
                    int n   = n0 + cc;
                    int s   = n / 384;
                    int rem = n - s * 384;
                    int h   = rem >> 5;
                    int d0  = rem & 31;
                    float sc = (s == 0) ? 0.17677669529663687f : 1.0f;
                    float* p = g_qkv + (size_t)s * SZ1 + h * 100352 + cBase[r] + d0;
                    *(float2*)p = make_float2(c0 * sc, c1 * sc);
                } else if (MODE == MODE_PROJ) {
                    int n = n0 + cc;
                    float* p = Cex + cBase[r] + n;
                    *(float2*)p = make_float2(c0 + g_bc[n], c1 + g_bc[n + 1]);
                } else {
                    float* p = g_Wc + cBase[r] + n0 + cc;
                    *(float2*)p = make_float2(c0, c1);
                }
            }
        }
    }
}

__global__ void bias_comb_kernel(const float* __restrict__ b_out,
                                 const float* __restrict__ w_post,
                                 const float* __restrict__ b_post)
{
    int j = blockIdx.x * blockDim.x + threadIdx.x;
    if (j < 384) {
        float s = b_post[j];
        for (int k = 0; k < 384; k++) s += b_out[k] * w_post[k * 384 + j];
        g_bc[j] = s;
    }
}

// One block per (b, head, window). 8 warps; warp owns rows i, i+8, ...
__global__ __launch_bounds__(256)
void attn_kernel(const float* __restrict__ pe)
{
    __shared__ __align__(16) float qs[49 * 36];
    __shared__ __align__(16) float ks[49 * 36];
    __shared__ __align__(16) float vs[49 * 36];
    __shared__ __align__(16) float ps[8][52];
    __shared__ float pes[169];

    const int tid = threadIdx.x;
    const int bw  = blockIdx.x;
    const int win = bw & 63;
    const int bh  = bw >> 6;
    const int h   = bh % 12;
    const int b   = bh / 12;
    const size_t base = (size_t)bw * 1568;

    // vectorized stage: 1568 floats = 392 float4 per tensor
    {
        const float4* gq = (const float4*)(g_qkv + base);
        const float4* gk = (const float4*)(g_qkv + (size_t)SZ1 + base);
        const float4* gv = (const float4*)(g_qkv + 2u * (size_t)SZ1 + base);
        for (int i4 = tid; i4 < 392; i4 += 256) {
            int r = i4 >> 3;            // 8 float4 per 32-float row
            int c = (i4 & 7) * 4;
            int o = r * 36 + c;         // 16B-aligned (144r + 16(c/4))
            *(float4*)(qs + o) = gq[i4];
            *(float4*)(ks + o) = gk[i4];
            *(float4*)(vs + o) = gv[i4];
        }
    }
    if (tid < 169) pes[tid] = pe[tid];
    __syncthreads();

    const bool mUL = (win >= 56);
    const bool mLR = ((win & 7) == 7);
    const int warp = tid >> 5, lane = tid & 31;
    const int j0 = lane;
    const int j1 = lane + 32;
    const bool j1v = (j1 < 49);
    const int j1c = j1v ? j1 : 48;
    const int xj0 = j0 / 7,  yj0 = j0  - xj0 * 7;
    const int xj1 = j1c / 7, yj1 = j1c - xj1 * 7;
    const int wy = win >> 3, wx = win & 7;

    const float4* ka4 = (const float4*)(ks + j0  * 36);
    const float4* kb4 = (const float4*)(ks + j1c * 36);

    for (int i = warp; i < 49; i += 8) {
        const int xi = i / 7, yi = i - xi * 7;
        const float4* q4 = (const float4*)(qs + i * 36);
        float s0 = 0.f, s1 = 0.f;
#pragma unroll
        for (int d = 0; d < 8; d++) {
            float4 q = q4[d], A = ka4[d], Bv = kb4[d];
            s0 += q.x * A.x  + q.y * A.y  + q.z * A.z  + q.w * A.w;
            s1 += q.x * Bv.x + q.y * Bv.y + q.z * Bv.z + q.w * Bv.w;
        }
        s0 += pes[(xj0 - xi + 6) * 13 + (yj0 - yi + 6)];
        s1 += pes[(xj1 - xi + 6) * 13 + (yj1 - yi + 6)];
        if (mUL) {
            if ((i >= 28) != (j0  >= 28)) s0 = -1e30f;
            if ((i >= 28) != (j1c >= 28)) s1 = -1e30f;
        }
        if (mLR) {
            if ((yi >= 4) != (yj0 >= 4)) s0 = -1e30f;
            if ((yi >= 4) != (yj1 >= 4)) s1 = -1e30f;
        }
        if (!j1v) s1 = -1e30f;

        float mx = fmaxf(s0, s1);
#pragma unroll
        for (int o = 16; o > 0; o >>= 1)
            mx = fmaxf(mx, __shfl_xor_sync(0xffffffffu, mx, o));
        float e0 = __expf(s0 - mx);
        float e1 = j1v ? __expf(s1 - mx) : 0.f;
        float sum = e0 + e1;
#pragma unroll
        for (int o = 16; o > 0; o >>= 1)
            sum += __shfl_xor_sync(0xffffffffu, sum, o);
        float inv = 1.0f / sum;
        ps[warp][j0] = e0 * inv;
        if (j1v) ps[warp][j1] = e1 * inv;
        __syncwarp();

        const float4* p4 = (const float4*)&ps[warp][0];
        float acc = 0.f;
#pragma unroll
        for (int j4 = 0; j4 < 12; j4++) {
            float4 p = p4[j4];
            const float* v = vs + (j4 * 4) * 36 + lane;
            acc += p.x * v[0] + p.y * v[36] + p.z * v[72] + p.w * v[108];
        }
        acc += ps[warp][48] * vs[48 * 36 + lane];

        int hh = wy * 7 + xi, ww = wx * 7 + yi;
        size_t m = (size_t)(b * 56 + hh) * 56 + ww;
        g_attn[m * 384 + h * 32 + lane] = acc;
        __syncwarp();
    }
}

extern "C" void kernel_launch(void* const* d_in, const int* in_sizes, int n_in,
                              void* d_out, int out_size)
{
    const float* x     = (const float*)d_in[0];
    const float* wqkv  = (const float*)d_in[1];
    const float* pe    = (const float*)d_in[2];
    const float* wout  = (const float*)d_in[3];
    const float* bout  = (const float*)d_in[4];
    const float* wpost = (const float*)d_in[5];
    const float* bpost = (const float*)d_in[6];
    float* out = (float*)d_out;

    (void)in_sizes; (void)n_in; (void)out_size;

    tf32gemm<MODE_COMB><<<dim3(3, 3), 256>>>(wout, wpost, nullptr, 384, 384, 384);
    bias_comb_kernel<<<2, 192>>>(bout, wpost, bpost);

    tf32gemm<MODE_QKV><<<dim3(QKV_N / 128, M_TOK / 128), 256>>>(
        x, wqkv, nullptr, M_TOK, QKV_N, 384);

    attn_kernel<<<BATCH * NHEAD * NWIN, 256>>>(pe);

    tf32gemm<MODE_PROJ><<<dim3(DIM / 128, M_TOK / 128), 256>>>(
        nullptr, nullptr, out, M_TOK, DIM, 384);
}

// round 9
// speedup vs baseline: 3.4611x; 1.1892x over previous
#include <cuda_runtime.h>

// ---------------------------------------------------------------------------
// Swin shifted-window attention block.
//   K1: W_comb = w_out @ w_post  (tf32 mma)
//   K2: b_comb = b_out @ w_post + b_post
//   K3: qkv = roll(x,-3,-3) @ w_qkv  (tf32 mma), scattered windowed, q scaled
//   K4: per-(b,head,window) attention, fp32, row-batched per warp
//   K5: out = attn @ W_comb + b_comb (tf32 mma), scatter roll(+3,+3)
// ---------------------------------------------------------------------------

#define BATCH 16
#define HW    56
#define DIM   384
#define NHEAD 12
#define HDIM  32
#define NWIN  64
#define M_TOK (BATCH*HW*HW)            // 50176
#define QKV_N (3*NHEAD*HDIM)           // 1152
#define SZ1   (BATCH*NHEAD*NWIN*49*HDIM) // 19,267,584 per q/k/v

__device__ float g_qkv[3u * SZ1];
__device__ float g_attn[(size_t)M_TOK * DIM];
__device__ float g_Wc[DIM * DIM];
__device__ float g_bc[DIM];

#define MODE_COMB 0
#define MODE_QKV  1
#define MODE_PROJ 2

__device__ __forceinline__ float f2tf(float x) {
    unsigned r;
    asm("cvt.rna.tf32.f32 %0, %1;" : "=r"(r) : "f"(x));
    return __uint_as_float(r);
}

__device__ __forceinline__ void mma_tf32(float* c, const float* a, const float* b) {
    asm volatile(
        "mma.sync.aligned.m16n8k8.row.col.f32.tf32.tf32.f32 "
        "{%0,%1,%2,%3}, {%4,%5,%6,%7}, {%8,%9}, {%0,%1,%2,%3};\n"
        : "+f"(c[0]), "+f"(c[1]), "+f"(c[2]), "+f"(c[3])
        : "r"(__float_as_uint(a[0])), "r"(__float_as_uint(a[1])),
          "r"(__float_as_uint(a[2])), "r"(__float_as_uint(a[3])),
          "r"(__float_as_uint(b[0])), "r"(__float_as_uint(b[1])));
}

// 128x128 block tile, warp tile 64x32 (warpM 0..1, warpN 0..3), K-chunk 16,
// double-buffered shared. K == 384 always.
template <int MODE>
__global__ __launch_bounds__(256)
void tf32gemm(const float* __restrict__ Aex,
              const float* __restrict__ Bex,
              float* __restrict__ Cex,
              int M, int N, int K)
{
    const float* A = (MODE == MODE_PROJ) ? g_attn : Aex;
    const float* B = (MODE == MODE_PROJ) ? g_Wc  : Bex;

    __shared__ __align__(16) float As[2][128][20];
    __shared__ __align__(16) float Bs[2][16][136];
    __shared__ int aOffS[128];
    __shared__ int cBase[128];

    const int tid = threadIdx.x;
    const int m0  = blockIdx.y * 128;
    const int n0  = blockIdx.x * 128;

    if (tid < 128) {
        int m = m0 + tid;
        if (MODE == MODE_COMB) {
            aOffS[tid] = m * 384;
            cBase[tid] = m * N;
        } else {
            int b = m / 3136;
            int t = m - b * 3136;
            int hh = t / 56, ww = t - (t / 56) * 56;
            if (MODE == MODE_QKV) {
                int sh = hh + 3; if (sh >= 56) sh -= 56;   // roll(-3)
                int sw = ww + 3; if (sw >= 56) sw -= 56;
                aOffS[tid] = ((b * 56 + sh) * 56 + sw) * 384;
                int wy = hh / 7, xi = hh - wy * 7;
                int wx = ww / 7, yi = ww - wx * 7;
                cBase[tid] = (b * 768 + wy * 8 + wx) * 1568 + (xi * 7 + yi) * 32;
            } else {
                aOffS[tid] = m * 384;
                int dh = hh + 3; if (dh >= 56) dh -= 56;   // roll(+3)
                int dw = ww + 3; if (dw >= 56) dw -= 56;
                cBase[tid] = ((b * 56 + dh) * 56 + dw) * 384;
            }
        }
    }
    __syncthreads();

    const int aRow = tid >> 1, aCol = (tid & 1) * 8;
    const int bRow = tid >> 4, bCol = (tid & 15) * 8;
    const int lane = tid & 31, grp = lane >> 2, qk = lane & 3;
    const int warpId = tid >> 5;
    const int warpM = warpId & 1;     // *64
    const int warpN = warpId >> 1;    // *32

    const float* aPtr = A + aOffS[aRow] + aCol;
    const float* bPtr = B + (size_t)bRow * N + n0 + bCol;

    float acc[4][4][4];
#pragma unroll
    for (int i = 0; i < 4; i++)
#pragma unroll
        for (int j = 0; j < 4; j++)
#pragma unroll
            for (int r = 0; r < 4; r++) acc[i][j][r] = 0.f;

    float4 ra0 = *(const float4*)(aPtr);
    float4 ra1 = *(const float4*)(aPtr + 4);
    float4 rb0 = *(const float4*)(bPtr);
    float4 rb1 = *(const float4*)(bPtr + 4);

    // stage chunk 0 -> buf 0
    {
        float* d = &As[0][aRow][aCol];
        d[0]=f2tf(ra0.x); d[1]=f2tf(ra0.y); d[2]=f2tf(ra0.z); d[3]=f2tf(ra0.w);
        d[4]=f2tf(ra1.x); d[5]=f2tf(ra1.y); d[6]=f2tf(ra1.z); d[7]=f2tf(ra1.w);
        float* e = &Bs[0][bRow][bCol];
        e[0]=f2tf(rb0.x); e[1]=f2tf(rb0.y); e[2]=f2tf(rb0.z); e[3]=f2tf(rb0.w);
        e[4]=f2tf(rb1.x); e[5]=f2tf(rb1.y); e[6]=f2tf(rb1.z); e[7]=f2tf(rb1.w);
    }
    __syncthreads();

    const int NK = 384 / 16;  // 24
    int buf = 0;
    for (int kc = 0; kc < NK; kc++) {
        if (kc + 1 < NK) {
            const float* ap = aPtr + (kc + 1) * 16;
            const float* bp = bPtr + (size_t)(kc + 1) * 16 * N;
            ra0 = *(const float4*)(ap);
            ra1 = *(const float4*)(ap + 4);
            rb0 = *(const float4*)(bp);
            rb1 = *(const float4*)(bp + 4);
        }

#pragma unroll
        for (int s = 0; s < 16; s += 8) {
            float af[4][4], bf[4][2];
#pragma unroll
            for (int mi = 0; mi < 4; mi++) {
                int r = warpM * 64 + mi * 16 + grp;
                af[mi][0] = As[buf][r][s + qk];
                af[mi][1] = As[buf][r + 8][s + qk];
                af[mi][2] = As[buf][r][s + qk + 4];
                af[mi][3] = As[buf][r + 8][s + qk + 4];
            }
#pragma unroll
            for (int ni = 0; ni < 4; ni++) {
                int c = warpN * 32 + ni * 8 + grp;
                bf[ni][0] = Bs[buf][s + qk][c];
                bf[ni][1] = Bs[buf][s + qk + 4][c];
            }
#pragma unroll
            for (int mi = 0; mi < 4; mi++)
#pragma unroll
                for (int ni = 0; ni < 4; ni++)
                    mma_tf32(acc[mi][ni], af[mi], bf[ni]);
        }

        if (kc + 1 < NK) {
            int nb = buf ^ 1;
            float* d = &As[nb][aRow][aCol];
            d[0]=f2tf(ra0.x); d[1]=f2tf(ra0.y); d[2]=f2tf(ra0.z); d[3]=f2tf(ra0.w);
            d[4]=f2tf(ra1.x); d[5]=f2tf(ra1.y); d[6]=f2tf(ra1.z); d[7]=f2tf(ra1.w);
            float* e = &Bs[nb][bRow][bCol];
            e[0]=f2tf(rb0.x); e[1]=f2tf(rb0.y); e[2]=f2tf(rb0.z); e[3]=f2tf(rb0.w);
            e[4]=f2tf(rb1.x); e[5]=f2tf(rb1.y); e[6]=f2tf(rb1.z); e[7]=f2tf(rb1.w);
        }
        __syncthreads();
        buf ^= 1;
    }

    // ---- epilogue ----
#pragma unroll
    for (int mi = 0; mi < 4; mi++) {
        int r0r = warpM * 64 + mi * 16 + grp;
#pragma unroll
        for (int half = 0; half < 2; half++) {
            int r = r0r + half * 8;
#pragma unroll
            for (int ni = 0; ni < 4; ni++) {
                int cc = warpN * 32 + ni * 8 + qk * 2;
                float c0 = acc[mi][ni][half * 2 + 0];
                float c1 = acc[mi][ni][half * 2 + 1];
                if (MODE == MODE_QKV) {
                    int n   = n0 + cc;
                    int s   = n / 384;
                    int rem = n - s * 384;
                    int h   = rem >> 5;
                    int d0  = rem & 31;
                    float sc = (s == 0) ? 0.17677669529663687f : 1.0f;
                    float* p = g_qkv + (size_t)s * SZ1 + h * 100352 + cBase[r] + d0;
                    *(float2*)p = make_float2(c0 * sc, c1 * sc);
                } else if (MODE == MODE_PROJ) {
                    int n = n0 + cc;
                    float* p = Cex + cBase[r] + n;
                    *(float2*)p = make_float2(c0 + g_bc[n], c1 + g_bc[n + 1]);
                } else {
                    float* p = g_Wc + cBase[r] + n0 + cc;
                    *(float2*)p = make_float2(c0, c1);
                }
            }
        }
    }
}

__global__ void bias_comb_kernel(const float* __restrict__ b_out,
                                 const float* __restrict__ w_post,
                                 const float* __restrict__ b_post)
{
    int j = blockIdx.x * blockDim.x + threadIdx.x;
    if (j < 384) {
        float s = b_post[j];
        for (int k = 0; k < 384; k++) s += b_out[k] * w_post[k * 384 + j];
        g_bc[j] = s;
    }
}

// One block per (b, head, window). 8 warps; warp w owns rows w, w+8, ...
// All of a warp's rows are processed together so K/V smem reads are shared.
__global__ __launch_bounds__(256)
void attn_kernel(const float* __restrict__ pe)
{
    __shared__ __align__(16) float qs[49 * 36];
    __shared__ __align__(16) float ks[49 * 36];
    __shared__ __align__(16) float vs[49 * 36];
    __shared__ __align__(16) float ps[49 * 52];   // probs, row-major, pitch 52
    __shared__ float pes[169];

    const int tid = threadIdx.x;
    const int bw  = blockIdx.x;
    const int win = bw & 63;
    const int bh  = bw >> 6;
    const int h   = bh % 12;
    const int b   = bh / 12;
    const size_t base = (size_t)bw * 1568;

    {
        const float4* gq = (const float4*)(g_qkv + base);
        const float4* gk = (const float4*)(g_qkv + (size_t)SZ1 + base);
        const float4* gv = (const float4*)(g_qkv + 2u * (size_t)SZ1 + base);
        for (int i4 = tid; i4 < 392; i4 += 256) {
            int r = i4 >> 3;
            int c = (i4 & 7) * 4;
            int o = r * 36 + c;
            *(float4*)(qs + o) = gq[i4];
            *(float4*)(ks + o) = gk[i4];
            *(float4*)(vs + o) = gv[i4];
        }
    }
    if (tid < 169) pes[tid] = pe[tid];
    __syncthreads();

    const bool mUL = (win >= 56);
    const bool mLR = ((win & 7) == 7);
    const int warp = tid >> 5, lane = tid & 31;
    const int j0 = lane;
    const int j1 = lane + 32;
    const bool j1v = (j1 < 49);
    const int j1c = j1v ? j1 : 48;
    const int xj0 = j0 / 7,  yj0 = j0  - xj0 * 7;
    const int xj1 = j1c / 7, yj1 = j1c - xj1 * 7;
    const int wy = win >> 3, wx = win & 7;

    const int NR = (warp == 0) ? 7 : 6;   // rows: warp + 8*rr < 49

    // ---- Phase A: QK^T for all rows of this warp, K read once ----
    float S0[7], S1[7];
#pragma unroll
    for (int rr = 0; rr < 7; rr++) { S0[rr] = 0.f; S1[rr] = 0.f; }

    const float4* ka4 = (const float4*)(ks + j0  * 36);
    const float4* kb4 = (const float4*)(ks + j1c * 36);
#pragma unroll
    for (int d4 = 0; d4 < 8; d4++) {
        float4 A = ka4[d4], Bv = kb4[d4];
#pragma unroll
        for (int rr = 0; rr < 7; rr++) {
            int i = warp + rr * 8;
            if (rr < NR) {
                float4 q = *(const float4*)(qs + i * 36 + d4 * 4);  // broadcast
                S0[rr] += q.x * A.x  + q.y * A.y  + q.z * A.z  + q.w * A.w;
                S1[rr] += q.x * Bv.x + q.y * Bv.y + q.z * Bv.z + q.w * Bv.w;
            }
        }
    }

    // ---- softmax per row, probs -> ps ----
#pragma unroll
    for (int rr = 0; rr < 7; rr++) {
        if (rr >= NR) break;
        const int i = warp + rr * 8;
        const int xi = i / 7, yi = i - xi * 7;
        float s0 = S0[rr] + pes[(xj0 - xi + 6) * 13 + (yj0 - yi + 6)];
        float s1 = S1[rr] + pes[(xj1 - xi + 6) * 13 + (yj1 - yi + 6)];
        if (mUL) {
            if ((i >= 28) != (j0  >= 28)) s0 = -1e30f;
            if ((i >= 28) != (j1c >= 28)) s1 = -1e30f;
        }
        if (mLR) {
            if ((yi >= 4) != (yj0 >= 4)) s0 = -1e30f;
            if ((yi >= 4) != (yj1 >= 4)) s1 = -1e30f;
        }
        if (!j1v) s1 = -1e30f;

        float mx = fmaxf(s0, s1);
#pragma unroll
        for (int o = 16; o > 0; o >>= 1)
            mx = fmaxf(mx, __shfl_xor_sync(0xffffffffu, mx, o));
        float e0 = __expf(s0 - mx);
        float e1 = j1v ? __expf(s1 - mx) : 0.f;
        float sum = e0 + e1;
#pragma unroll
        for (int o = 16; o > 0; o >>= 1)
            sum += __shfl_xor_sync(0xffffffffu, sum, o);
        float inv = 1.0f / sum;
        ps[i * 52 + j0] = e0 * inv;
        if (j1v) ps[i * 52 + j1] = e1 * inv;
    }
    __syncwarp();   // warp only reads its own rows below

    // ---- Phase B: PV for all rows, V read once ----
    float acc[7];
#pragma unroll
    for (int rr = 0; rr < 7; rr++) acc[rr] = 0.f;

#pragma unroll
    for (int j4 = 0; j4 < 12; j4++) {
        float v0 = vs[(j4 * 4 + 0) * 36 + lane];
        float v1 = vs[(j4 * 4 + 1) * 36 + lane];
        float v2 = vs[(j4 * 4 + 2) * 36 + lane];
        float v3 = vs[(j4 * 4 + 3) * 36 + lane];
#pragma unroll
        for (int rr = 0; rr < 7; rr++) {
            if (rr < NR) {
                int i = warp + rr * 8;
                float4 p = *(const float4*)(ps + i * 52 + j4 * 4);  // broadcast
                acc[rr] += p.x * v0 + p.y * v1 + p.z * v2 + p.w * v3;
            }
        }
    }
    {
        float v48 = vs[48 * 36 + lane];
#pragma unroll
        for (int rr = 0; rr < 7; rr++)
            if (rr < NR) acc[rr] += ps[(warp + rr * 8) * 52 + 48] * v48;
    }

    // ---- store (merge windows, still shifted coords) ----
#pragma unroll
    for (int rr = 0; rr < 7; rr++) {
        if (rr >= NR) break;
        const int i = warp + rr * 8;
        const int xi = i / 7, yi = i - xi * 7;
        int hh = wy * 7 + xi, ww = wx * 7 + yi;
        size_t m = (size_t)(b * 56 + hh) * 56 + ww;
        g_attn[m * 384 + h * 32 + lane] = acc[rr];
    }
}

extern "C" void kernel_launch(void* const* d_in, const int* in_sizes, int n_in,
                              void* d_out, int out_size)
{
    const float* x     = (const float*)d_in[0];
    const float* wqkv  = (const float*)d_in[1];
    const float* pe    = (const float*)d_in[2];
    const float* wout  = (const float*)d_in[3];
    const float* bout  = (const float*)d_in[4];
    const float* wpost = (const float*)d_in[5];
    const float* bpost = (const float*)d_in[6];
    float* out = (float*)d_out;

    (void)in_sizes; (void)n_in; (void)out_size;

    tf32gemm<MODE_COMB><<<dim3(3, 3), 256>>>(wout, wpost, nullptr, 384, 384, 384);
    bias_comb_kernel<<<2, 192>>>(bout, wpost, bpost);

    tf32gemm<MODE_QKV><<<dim3(QKV_N / 128, M_TOK / 128), 256>>>(
        x, wqkv, nullptr, M_TOK, QKV_N, 384);

    attn_kernel<<<BATCH * NHEAD * NWIN, 256>>>(pe);

    tf32gemm<MODE_PROJ><<<dim3(DIM / 128, M_TOK / 128), 256>>>(
        nullptr, nullptr, out, M_TOK, DIM, 384);
}

// round 15
// speedup vs baseline: 4.1762x; 1.2066x over previous
#include <cuda_runtime.h>
#include <cstdint>
#include <cuda_fp16.h>

// ---------------------------------------------------------------------------
// Swin shifted-window attention block. fp16 mma.sync (m16n8k16) GEMMs.
//   K0: g_BtQ = w_qkv^T                    (fp32 transpose)
//   K1: g_WcT = (w_out @ w_post)^T         (SIMT tf32 mma, tiny)
//   K2: g_bc  = b_out @ w_post + b_post
//   K3: g_qkv = x @ w_qkv  (linear, fp16 mma, q cols scaled)
//   K4: attention; cyclic roll folded into token gather (linear qkv/attn)
//   K5: out = g_attn @ Wc + bc  (linear, fp16 mma)
// ---------------------------------------------------------------------------

#define M_TOK (16*56*56)               // 50176
#define QKV_N 1152

__device__ float g_qkv[(size_t)M_TOK * QKV_N];  // [m][1152] linear
__device__ float g_attn[(size_t)M_TOK * 384];   // [m][384] linear
__device__ float g_BtQ[QKV_N * 384];            // w_qkv^T  [1152][384]
__device__ float g_WcT[384 * 384];              // (wout@wpost)^T [384][384]
__device__ float g_bc[384];

__device__ __forceinline__ float f2tf(float x) {
    unsigned r;
    asm("cvt.rna.tf32.f32 %0, %1;" : "=r"(r) : "f"(x));
    return __uint_as_float(r);
}
// pack two fp32 -> half2 {lo=x, hi=y}
__device__ __forceinline__ unsigned f2h2(float x, float y) {
    unsigned r;
    asm("cvt.rn.f16x2.f32 %0, %1, %2;" : "=r"(r) : "f"(y), "f"(x));
    return r;
}

__device__ __forceinline__ void mma_f16(float* c, const unsigned* a, const unsigned* b) {
    asm volatile(
        "mma.sync.aligned.m16n8k16.row.col.f32.f16.f16.f32 "
        "{%0,%1,%2,%3}, {%4,%5,%6,%7}, {%8,%9}, {%0,%1,%2,%3};\n"
        : "+f"(c[0]), "+f"(c[1]), "+f"(c[2]), "+f"(c[3])
        : "r"(a[0]), "r"(a[1]), "r"(a[2]), "r"(a[3]), "r"(b[0]), "r"(b[1]));
}

// ---------------------------------------------------------------------------
// fp16 GEMM: C[m0..m0+127][n0..n0+127] = A[128][384] @ Bt^T
// A row-major [M][384] fp32, Bt [N][384] fp32 (K-major). Block 128x128,
// 8 warps (warpM 0..1 x warpN 0..3 -> warp tile 64x32), K-chunk 16, dbl-buf.
// ---------------------------------------------------------------------------
template <int IS_QKV>
__global__ __launch_bounds__(256)
void h16gemm(const float* __restrict__ A, const float* __restrict__ Bt,
             float* __restrict__ C, int cStride)
{
    // smem: half2 words as unsigned, [buf][kpair(8)][pitch 132]
    __shared__ unsigned As2[2][8][132];
    __shared__ unsigned Bs2[2][8][132];

    const int tid = threadIdx.x;
    const int m0  = blockIdx.y * 128;
    const int n0  = blockIdx.x * 128;

    const int lane = tid & 31, grp = lane >> 2, qk = lane & 3;
    const int warpId = tid >> 5;
    const int warpM = warpId & 1;     // *64
    const int warpN = warpId >> 1;    // *32

    // staging: i4 in [0,512): row = i4>>2 (0..127), seg = i4&3 (k quad of 4)
    const int r0 = tid >> 2, sg0 = tid & 3;              // i4 = tid
    const int r1 = (tid + 256) >> 2, sg1 = tid & 3;      // i4 = tid+256

    const float* Ab = A + (size_t)m0 * 384;
    const float* Bb = Bt + (size_t)n0 * 384;

    float acc[4][4][4];
#pragma unroll
    for (int i = 0; i < 4; i++)
#pragma unroll
        for (int j = 0; j < 4; j++)
#pragma unroll
            for (int r = 0; r < 4; r++) acc[i][j][r] = 0.f;

    float4 ra0 = *(const float4*)(Ab + (size_t)r0 * 384 + sg0 * 4);
    float4 ra1 = *(const float4*)(Ab + (size_t)r1 * 384 + sg1 * 4);
    float4 rb0 = *(const float4*)(Bb + (size_t)r0 * 384 + sg0 * 4);
    float4 rb1 = *(const float4*)(Bb + (size_t)r1 * 384 + sg1 * 4);

    // stage chunk 0 -> buf 0
    As2[0][sg0 * 2 + 0][r0] = f2h2(ra0.x, ra0.y);
    As2[0][sg0 * 2 + 1][r0] = f2h2(ra0.z, ra0.w);
    As2[0][sg1 * 2 + 0][r1] = f2h2(ra1.x, ra1.y);
    As2[0][sg1 * 2 + 1][r1] = f2h2(ra1.z, ra1.w);
    Bs2[0][sg0 * 2 + 0][r0] = f2h2(rb0.x, rb0.y);
    Bs2[0][sg0 * 2 + 1][r0] = f2h2(rb0.z, rb0.w);
    Bs2[0][sg1 * 2 + 0][r1] = f2h2(rb1.x, rb1.y);
    Bs2[0][sg1 * 2 + 1][r1] = f2h2(rb1.z, rb1.w);
    __syncthreads();

    const int NK = 24;               // 384 / 16
    int buf = 0;
    for (int kc = 0; kc < NK; kc++) {
        if (kc + 1 < NK) {
            const int k0 = (kc + 1) * 16;
            ra0 = *(const float4*)(Ab + (size_t)r0 * 384 + k0 + sg0 * 4);
            ra1 = *(const float4*)(Ab + (size_t)r1 * 384 + k0 + sg1 * 4);
            rb0 = *(const float4*)(Bb + (size_t)r0 * 384 + k0 + sg0 * 4);
            rb1 = *(const float4*)(Bb + (size_t)r1 * 384 + k0 + sg1 * 4);
        }

        unsigned aF[4][4], bF[4][2];
#pragma unroll
        for (int mi = 0; mi < 4; mi++) {
            int r = warpM * 64 + mi * 16 + grp;
            aF[mi][0] = As2[buf][qk][r];
            aF[mi][1] = As2[buf][qk][r + 8];
            aF[mi][2] = As2[buf][qk + 4][r];
            aF[mi][3] = As2[buf][qk + 4][r + 8];
        }
#pragma unroll
        for (int ni = 0; ni < 4; ni++) {
            int c = warpN * 32 + ni * 8 + grp;
            bF[ni][0] = Bs2[buf][qk][c];
            bF[ni][1] = Bs2[buf][qk + 4][c];
        }
#pragma unroll
        for (int mi = 0; mi < 4; mi++)
#pragma unroll
            for (int ni = 0; ni < 4; ni++)
                mma_f16(acc[mi][ni], aF[mi], bF[ni]);

        if (kc + 1 < NK) {
            int nb = buf ^ 1;
            As2[nb][sg0 * 2 + 0][r0] = f2h2(ra0.x, ra0.y);
            As2[nb][sg0 * 2 + 1][r0] = f2h2(ra0.z, ra0.w);
            As2[nb][sg1 * 2 + 0][r1] = f2h2(ra1.x, ra1.y);
            As2[nb][sg1 * 2 + 1][r1] = f2h2(ra1.z, ra1.w);
            Bs2[nb][sg0 * 2 + 0][r0] = f2h2(rb0.x, rb0.y);
            Bs2[nb][sg0 * 2 + 1][r0] = f2h2(rb0.z, rb0.w);
            Bs2[nb][sg1 * 2 + 0][r1] = f2h2(rb1.x, rb1.y);
            Bs2[nb][sg1 * 2 + 1][r1] = f2h2(rb1.z, rb1.w);
        }
        __syncthreads();
        buf ^= 1;
    }

    // ---- epilogue (linear C) ----
    const bool doScale = IS_QKV && (n0 < 384);     // q columns
    const float qsc = doScale ? 0.17677669529663687f : 1.0f;
#pragma unroll
    for (int mi = 0; mi < 4; mi++) {
        int r0r = warpM * 64 + mi * 16 + grp;
#pragma unroll
        for (int half = 0; half < 2; half++) {
            int r = r0r + half * 8;
#pragma unroll
            for (int ni = 0; ni < 4; ni++) {
                int cc = warpN * 32 + ni * 8 + qk * 2;
                float c0 = acc[mi][ni][half * 2 + 0];
                float c1 = acc[mi][ni][half * 2 + 1];
                float* p = C + (size_t)(m0 + r) * cStride + n0 + cc;
                if (IS_QKV) {
                    *(float2*)p = make_float2(c0 * qsc, c1 * qsc);
                } else {
                    *(float2*)p = make_float2(c0 + g_bc[n0 + cc],
                                              c1 + g_bc[n0 + cc + 1]);
                }
            }
        }
    }
}

// ---------------- weight transpose: Bt[n][k] = W[k][n] (fp32) --------------
__global__ void transposeB(const float* __restrict__ W, float* __restrict__ Bt,
                           int K, int N)
{
    __shared__ float t[32][33];
    int k0 = blockIdx.y * 32, n0 = blockIdx.x * 32;
    int x = threadIdx.x, y = threadIdx.y;
#pragma unroll
    for (int i = 0; i < 32; i += 8)
        t[y + i][x] = W[(size_t)(k0 + y + i) * N + n0 + x];
    __syncthreads();
#pragma unroll
    for (int i = 0; i < 32; i += 8)
        Bt[(size_t)(n0 + y + i) * K + k0 + x] = t[x][y + i];
}

// ---------------- COMB: g_WcT = (wout @ wpost)^T  (SIMT tf32 mma) ----------
__device__ __forceinline__ void mma_tf32(float* c, const float* a, const float* b) {
    asm volatile(
        "mma.sync.aligned.m16n8k8.row.col.f32.tf32.tf32.f32 "
        "{%0,%1,%2,%3}, {%4,%5,%6,%7}, {%8,%9}, {%0,%1,%2,%3};\n"
        : "+f"(c[0]), "+f"(c[1]), "+f"(c[2]), "+f"(c[3])
        : "r"(__float_as_uint(a[0])), "r"(__float_as_uint(a[1])),
          "r"(__float_as_uint(a[2])), "r"(__float_as_uint(a[3])),
          "r"(__float_as_uint(b[0])), "r"(__float_as_uint(b[1])));
}

__global__ __launch_bounds__(256)
void comb_gemm(const float* __restrict__ A, const float* __restrict__ B)
{
    __shared__ __align__(16) float As[2][128][20];
    __shared__ __align__(16) float Bs[2][16][136];
    const int tid = threadIdx.x;
    const int m0 = blockIdx.y * 128, n0 = blockIdx.x * 128;
    const int N = 384;

    const int aRow = tid >> 1, aCol = (tid & 1) * 8;
    const int bRow = tid >> 4, bCol = (tid & 15) * 8;
    const int lane = tid & 31, grp = lane >> 2, qk = lane & 3;
    const int warpId = tid >> 5;
    const int warpM = warpId & 1, warpN = warpId >> 1;

    const float* aPtr = A + (size_t)(m0 + aRow) * 384 + aCol;
    const float* bPtr = B + (size_t)bRow * N + n0 + bCol;

    float acc[4][4][4];
#pragma unroll
    for (int i = 0; i < 4; i++)
#pragma unroll
        for (int j = 0; j < 4; j++)
#pragma unroll
            for (int r = 0; r < 4; r++) acc[i][j][r] = 0.f;

    float4 ra0 = *(const float4*)(aPtr);
    float4 ra1 = *(const float4*)(aPtr + 4);
    float4 rb0 = *(const float4*)(bPtr);
    float4 rb1 = *(const float4*)(bPtr + 4);
    {
        float* d = &As[0][aRow][aCol];
        d[0]=f2tf(ra0.x); d[1]=f2tf(ra0.y); d[2]=f2tf(ra0.z); d[3]=f2tf(ra0.w);
        d[4]=f2tf(ra1.x); d[5]=f2tf(ra1.y); d[6]=f2tf(ra1.z); d[7]=f2tf(ra1.w);
        float* e = &Bs[0][bRow][bCol];
        e[0]=f2tf(rb0.x); e[1]=f2tf(rb0.y); e[2]=f2tf(rb0.z); e[3]=f2tf(rb0.w);
        e[4]=f2tf(rb1.x); e[5]=f2tf(rb1.y); e[6]=f2tf(rb1.z); e[7]=f2tf(rb1.w);
    }
    __syncthreads();

    const int NK = 24;
    int buf = 0;
    for (int kc = 0; kc < NK; kc++) {
        if (kc + 1 < NK) {
            const float* ap = aPtr + (kc + 1) * 16;
            const float* bp = bPtr + (size_t)(kc + 1) * 16 * N;
            ra0 = *(const float4*)(ap);
            ra1 = *(const float4*)(ap + 4);
            rb0 = *(const float4*)(bp);
            rb1 = *(const float4*)(bp + 4);
        }
#pragma unroll
        for (int s = 0; s < 16; s += 8) {
            float af[4][4], bf[4][2];
#pragma unroll
            for (int mi = 0; mi < 4; mi++) {
                int r = warpM * 64 + mi * 16 + grp;
                af[mi][0] = As[buf][r][s + qk];
                af[mi][1] = As[buf][r + 8][s + qk];
                af[mi][2] = As[buf][r][s + qk + 4];
                af[mi][3] = As[buf][r + 8][s + qk + 4];
            }
#pragma unroll
            for (int ni = 0; ni < 4; ni++) {
                int c = warpN * 32 + ni * 8 + grp;
                bf[ni][0] = Bs[buf][s + qk][c];
                bf[ni][1] = Bs[buf][s + qk + 4][c];
            }
#pragma unroll
            for (int mi = 0; mi < 4; mi++)
#pragma unroll
                for (int ni = 0; ni < 4; ni++)
                    mma_tf32(acc[mi][ni], af[mi], bf[ni]);
        }
        if (kc + 1 < NK) {
            int nb2 = buf ^ 1;
            float* d = &As[nb2][aRow][aCol];
            d[0]=f2tf(ra0.x); d[1]=f2tf(ra0.y); d[2]=f2tf(ra0.z); d[3]=f2tf(ra0.w);
            d[4]=f2tf(ra1.x); d[5]=f2tf(ra1.y); d[6]=f2tf(ra1.z); d[7]=f2tf(ra1.w);
            float* e = &Bs[nb2][bRow][bCol];
            e[0]=f2tf(rb0.x); e[1]=f2tf(rb0.y); e[2]=f2tf(rb0.z); e[3]=f2tf(rb0.w);
            e[4]=f2tf(rb1.x); e[5]=f2tf(rb1.y); e[6]=f2tf(rb1.z); e[7]=f2tf(rb1.w);
        }
        __syncthreads();
        buf ^= 1;
    }
    // transposed store: g_WcT[n][m]
#pragma unroll
    for (int mi = 0; mi < 4; mi++) {
        int r0r = warpM * 64 + mi * 16 + grp;
#pragma unroll
        for (int half = 0; half < 2; half++) {
            int gm = m0 + r0r + half * 8;
#pragma unroll
            for (int ni = 0; ni < 4; ni++) {
                int cc = n0 + warpN * 32 + ni * 8 + qk * 2;
                g_WcT[(size_t)cc * 384 + gm]       = acc[mi][ni][half * 2 + 0];
                g_WcT[(size_t)(cc + 1) * 384 + gm] = acc[mi][ni][half * 2 + 1];
            }
        }
    }
}

__global__ void bias_comb_kernel(const float* __restrict__ b_out,
                                 const float* __restrict__ w_post,
                                 const float* __restrict__ b_post)
{
    int j = blockIdx.x * blockDim.x + threadIdx.x;
    if (j < 384) {
        float s = b_post[j];
        for (int k = 0; k < 384; k++) s += b_out[k] * w_post[k * 384 + j];
        g_bc[j] = s;
    }
}

// ---------------- attention (row-batched per warp, roll folded in gather) --
__global__ __launch_bounds__(256)
void attn_kernel(const float* __restrict__ pe)
{
    __shared__ __align__(16) float qs[49 * 36];
    __shared__ __align__(16) float ks[49 * 36];
    __shared__ __align__(16) float vs[49 * 36];
    __shared__ __align__(16) float ps[49 * 52];
    __shared__ float pes[169];
    __shared__ int   tok[49];

    const int tid = threadIdx.x;
    const int bw  = blockIdx.x;
    const int win = bw & 63;
    const int bh  = bw >> 6;
    const int h   = bh % 12;
    const int b   = bh / 12;
    const int wy = win >> 3, wx = win & 7;

    if (tid < 49) {
        int xi = tid / 7, yi = tid - xi * 7;
        int oh = wy * 7 + xi + 3; if (oh >= 56) oh -= 56;   // roll fold
        int ow = wx * 7 + yi + 3; if (ow >= 56) ow -= 56;
        tok[tid] = (b * 56 + oh) * 56 + ow;
    }
    if (tid < 169) pes[tid] = pe[tid];
    __syncthreads();

    for (int i4 = tid; i4 < 392; i4 += 256) {
        int r = i4 >> 3;
        int c = (i4 & 7) * 4;
        const float* src = g_qkv + (size_t)tok[r] * 1152 + h * 32 + c;
        int o = r * 36 + c;
        *(float4*)(qs + o) = *(const float4*)(src);
        *(float4*)(ks + o) = *(const float4*)(src + 384);
        *(float4*)(vs + o) = *(const float4*)(src + 768);
    }
    __syncthreads();

    const bool mUL = (win >= 56);
    const bool mLR = ((win & 7) == 7);
    const int warp = tid >> 5, lane = tid & 31;
    const int j0 = lane;
    const int j1 = lane + 32;
    const bool j1v = (j1 < 49);
    const int j1c = j1v ? j1 : 48;
    const int xj0 = j0 / 7,  yj0 = j0  - xj0 * 7;
    const int xj1 = j1c / 7, yj1 = j1c - xj1 * 7;

    const int NR = (warp == 0) ? 7 : 6;

    float S0[7], S1[7];
#pragma unroll
    for (int rr = 0; rr < 7; rr++) { S0[rr] = 0.f; S1[rr] = 0.f; }

    const float4* ka4 = (const float4*)(ks + j0  * 36);
    const float4* kb4 = (const float4*)(ks + j1c * 36);
#pragma unroll
    for (int d4 = 0; d4 < 8; d4++) {
        float4 A = ka4[d4], Bv = kb4[d4];
#pragma unroll
        for (int rr = 0; rr < 7; rr++) {
            int i = warp + rr * 8;
            if (rr < NR) {
                float4 q = *(const float4*)(qs + i * 36 + d4 * 4);
                S0[rr] += q.x * A.x  + q.y * A.y  + q.z * A.z  + q.w * A.w;
                S1[rr] += q.x * Bv.x + q.y * Bv.y + q.z * Bv.z + q.w * Bv.w;
            }
        }
    }

#pragma unroll
    for (int rr = 0; rr < 7; rr++) {
        if (rr >= NR) break;
        const int i = warp + rr * 8;
        const int xi = i / 7, yi = i - xi * 7;
        float s0 = S0[rr] + pes[(xj0 - xi + 6) * 13 + (yj0 - yi + 6)];
        float s1 = S1[rr] + pes[(xj1 - xi + 6) * 13 + (yj1 - yi + 6)];
        if (mUL) {
            if ((i >= 28) != (j0  >= 28)) s0 = -1e30f;
            if ((i >= 28) != (j1c >= 28)) s1 = -1e30f;
        }
        if (mLR) {
            if ((yi >= 4) != (yj0 >= 4)) s0 = -1e30f;
            if ((yi >= 4) != (yj1 >= 4)) s1 = -1e30f;
        }
        if (!j1v) s1 = -1e30f;

        float mx = fmaxf(s0, s1);
#pragma unroll
        for (int o = 16; o > 0; o >>= 1)
            mx = fmaxf(mx, __shfl_xor_sync(0xffffffffu, mx, o));
        float e0 = __expf(s0 - mx);
        float e1 = j1v ? __expf(s1 - mx) : 0.f;
        float sum = e0 + e1;
#pragma unroll
        for (int o = 16; o > 0; o >>= 1)
            sum += __shfl_xor_sync(0xffffffffu, sum, o);
        float inv = 1.0f / sum;
        ps[i * 52 + j0] = e0 * inv;
        if (j1v) ps[i * 52 + j1] = e1 * inv;
    }
    __syncwarp();

    float acc[7];
#pragma unroll
    for (int rr = 0; rr < 7; rr++) acc[rr] = 0.f;

#pragma unroll
    for (int j4 = 0; j4 < 12; j4++) {
        float v0 = vs[(j4 * 4 + 0) * 36 + lane];
        float v1 = vs[(j4 * 4 + 1) * 36 + lane];
        float v2 = vs[(j4 * 4 + 2) * 36 + lane];
        float v3 = vs[(j4 * 4 + 3) * 36 + lane];
#pragma unroll
        for (int rr = 0; rr < 7; rr++) {
            if (rr < NR) {
                int i = warp + rr * 8;
                float4 p = *(const float4*)(ps + i * 52 + j4 * 4);
                acc[rr] += p.x * v0 + p.y * v1 + p.z * v2 + p.w * v3;
            }
        }
    }
    {
        float v48 = vs[48 * 36 + lane];
#pragma unroll
        for (int rr = 0; rr < 7; rr++)
            if (rr < NR) acc[rr] += ps[(warp + rr * 8) * 52 + 48] * v48;
    }

#pragma unroll
    for (int rr = 0; rr < 7; rr++) {
        if (rr >= NR) break;
        const int i = warp + rr * 8;
        g_attn[(size_t)tok[i] * 384 + h * 32 + lane] = acc[rr];
    }
}

extern "C" void kernel_launch(void* const* d_in, const int* in_sizes, int n_in,
                              void* d_out, int out_size)
{
    const float* x     = (const float*)d_in[0];
    const float* wqkv  = (const float*)d_in[1];
    const float* pe    = (const float*)d_in[2];
    const float* wout  = (const float*)d_in[3];
    const float* bout  = (const float*)d_in[4];
    const float* wpost = (const float*)d_in[5];
    const float* bpost = (const float*)d_in[6];
    float* out = (float*)d_out;

    (void)in_sizes; (void)n_in; (void)out_size;

    float* g_BtQ_p;  cudaGetSymbolAddress((void**)&g_BtQ_p, g_BtQ);
    float* g_WcT_p;  cudaGetSymbolAddress((void**)&g_WcT_p, g_WcT);
    float* g_qkv_p;  cudaGetSymbolAddress((void**)&g_qkv_p, g_qkv);
    float* g_attn_p; cudaGetSymbolAddress((void**)&g_attn_p, g_attn);

    transposeB<<<dim3(36, 12), dim3(32, 8)>>>(wqkv, g_BtQ_p, 384, 1152);
    comb_gemm<<<dim3(3, 3), 256>>>(wout, wpost);
    bias_comb_kernel<<<2, 192>>>(bout, wpost, bpost);

    // qkv = x @ w_qkv (linear), q scaled
    h16gemm<1><<<dim3(9, 392), 256>>>(x, g_BtQ_p, g_qkv_p, 1152);

    attn_kernel<<<16 * 12 * 64, 256>>>(pe);

    // out = attn @ Wc + bc (linear)
    h16gemm<0><<<dim3(3, 392), 256>>>(g_attn_p, g_WcT_p, out, 384);
}

// round 17
// speedup vs baseline: 5.5548x; 1.3301x over previous
#include <cuda_runtime.h>
#include <cstdint>
#include <cuda_fp16.h>

// ---------------------------------------------------------------------------
// Swin shifted-window attention block. fp16 mma + ldmatrix + cp.async GEMMs.
//   K0a: g_xh   = half(x)
//   K0b: g_BtQh = half(w_qkv^T)
//   K1:  g_WcTh = half((w_out @ w_post)^T)   (SIMT tf32 mma, tiny)
//   K2:  g_bc   = b_out @ w_post + b_post
//   K3:  g_qkv  = xh @ w_qkv   (fp16 mma, fp32 out, q scaled)
//   K4:  attention (fp32); roll folded into gather; writes g_attnh (half)
//   K5:  out = attnh @ Wc + bc (fp16 mma, fp32 out)
// ---------------------------------------------------------------------------

#define M_TOK (16*56*56)               // 50176
#define QKV_N 1152

__device__ float  g_qkv[(size_t)M_TOK * QKV_N];
__device__ __half g_xh[(size_t)M_TOK * 384];
__device__ __half g_attnh[(size_t)M_TOK * 384];
__device__ __half g_BtQh[QKV_N * 384];
__device__ __half g_WcTh[384 * 384];
__device__ float  g_bc[384];

__device__ __forceinline__ float f2tf(float x) {
    unsigned r;
    asm("cvt.rna.tf32.f32 %0, %1;" : "=r"(r) : "f"(x));
    return __uint_as_float(r);
}
// pack two fp32 -> f16x2 {lo=x, hi=y}
__device__ __forceinline__ unsigned f2h2(float x, float y) {
    unsigned r;
    asm("cvt.rn.f16x2.f32 %0, %1, %2;" : "=r"(r) : "f"(y), "f"(x));
    return r;
}
__device__ __forceinline__ uint32_t smem_u32(const void* p) {
    uint32_t a;
    asm("{ .reg .u64 t; cvta.to.shared.u64 t, %1; cvt.u32.u64 %0, t; }"
        : "=r"(a) : "l"(p));
    return a;
}

__device__ __forceinline__ void mma_f16(float* c, const unsigned* a, const unsigned* b) {
    asm volatile(
        "mma.sync.aligned.m16n8k16.row.col.f32.f16.f16.f32 "
        "{%0,%1,%2,%3}, {%4,%5,%6,%7}, {%8,%9}, {%0,%1,%2,%3};\n"
        : "+f"(c[0]), "+f"(c[1]), "+f"(c[2]), "+f"(c[3])
        : "r"(a[0]), "r"(a[1]), "r"(a[2]), "r"(a[3]), "r"(b[0]), "r"(b[1]));
}
#define LDSM_X4(r0, r1, r2, r3, addr) \
    asm volatile("ldmatrix.sync.aligned.m8n8.x4.shared.b16 {%0,%1,%2,%3}, [%4];" \
                 : "=r"(r0), "=r"(r1), "=r"(r2), "=r"(r3) : "r"(addr))
#define CP_ASYNC16(dst, src) \
    asm volatile("cp.async.cg.shared.global [%0], [%1], 16;" :: "r"(dst), "l"(src))

// ---------------------------------------------------------------------------
// fp16 GEMM: C[m0..+127][n0..+127] = A[128][384] @ Bt^T (+bias / q-scale).
// A [M][384] half, Bt [N][384] half. 8 warps, warp tile 64x32, K-chunk 32,
// cp.async double-buffer, swizzled smem (64B rows, chunk ^= (row>>1)&3),
// ldmatrix.x4 fragment loads.
// ---------------------------------------------------------------------------
template <int IS_QKV>
__global__ __launch_bounds__(256)
void h16gemm(const __half* __restrict__ A, const __half* __restrict__ Bt,
             float* __restrict__ C, int cStride)
{
    __shared__ __align__(16) __half As[2][128 * 32];
    __shared__ __align__(16) __half Bs[2][128 * 32];

    const int tid = threadIdx.x;
    const int m0  = blockIdx.y * 128;
    const int n0  = blockIdx.x * 128;
    const int lane = tid & 31, grp = lane >> 2, qk = lane & 3;
    const int warpId = tid >> 5;
    const int warpM = warpId & 1;     // *64
    const int warpN = warpId >> 1;    // *32

    const uint32_t asb = smem_u32(&As[0][0]);
    const uint32_t bsb = smem_u32(&Bs[0][0]);

    // per-lane ldmatrix row constants
    int aOff[4], aSw[4];
#pragma unroll
    for (int mi = 0; mi < 4; mi++) {
        int row = warpM * 64 + mi * 16 + (lane & 15);
        aOff[mi] = row * 64;
        aSw[mi]  = (row >> 1) & 3;
    }
    int bOff[2], bSw[2];
#pragma unroll
    for (int nh = 0; nh < 2; nh++) {
        int nrow = warpN * 32 + nh * 16 + ((lane >> 4) & 1) * 8 + (lane & 7);
        bOff[nh] = nrow * 64;
        bSw[nh]  = (nrow >> 1) & 3;
    }
    const int aChunkLane = lane >> 4;          // 0 or 1
    const int bChunkLane = (lane >> 3) & 1;    // 0 or 1

    float acc[4][4][4];
#pragma unroll
    for (int i = 0; i < 4; i++)
#pragma unroll
        for (int j = 0; j < 4; j++)
#pragma unroll
            for (int r = 0; r < 4; r++) acc[i][j][r] = 0.f;

    // ---- staging (cp.async): unit u -> row = u>>2, chunk c = u&3 ----
    const __half* Ab = A + (size_t)m0 * 384;
    const __half* Bb = Bt + (size_t)n0 * 384;

#define STAGE_CHUNK(kc, buf)                                                     \
    {                                                                            \
        const int k0s = (kc) * 32;                                               \
        _Pragma("unroll")                                                        \
        for (int p = 0; p < 2; p++) {                                            \
            int u = tid + p * 256;                                               \
            int row = u >> 2, c = u & 3;                                         \
            uint32_t sw = (uint32_t)((c ^ ((row >> 1) & 3)) * 16);               \
            CP_ASYNC16(asb + (buf) * 8192 + row * 64 + sw,                       \
                       Ab + (size_t)row * 384 + k0s + c * 8);                    \
            CP_ASYNC16(bsb + (buf) * 8192 + row * 64 + sw,                       \
                       Bb + (size_t)row * 384 + k0s + c * 8);                    \
        }                                                                        \
        asm volatile("cp.async.commit_group;");                                  \
    }

    STAGE_CHUNK(0, 0);

    const int NKC = 12;               // 384 / 32
    for (int kc = 0; kc < NKC; kc++) {
        if (kc + 1 < NKC) {
            STAGE_CHUNK(kc + 1, (kc + 1) & 1);
            asm volatile("cp.async.wait_group 1;");
        } else {
            asm volatile("cp.async.wait_group 0;");
        }
        __syncthreads();

        const uint32_t ab = asb + (kc & 1) * 8192;
        const uint32_t bb = bsb + (kc & 1) * 8192;
#pragma unroll
        for (int s = 0; s < 2; s++) {
            unsigned aF[4][4], bF[4][2];
#pragma unroll
            for (int mi = 0; mi < 4; mi++) {
                uint32_t addr = ab + aOff[mi]
                              + (uint32_t)(((2 * s + aChunkLane) ^ aSw[mi]) << 4);
                LDSM_X4(aF[mi][0], aF[mi][1], aF[mi][2], aF[mi][3], addr);
            }
#pragma unroll
            for (int nh = 0; nh < 2; nh++) {
                uint32_t addr = bb + bOff[nh]
                              + (uint32_t)(((2 * s + bChunkLane) ^ bSw[nh]) << 4);
                LDSM_X4(bF[nh * 2][0], bF[nh * 2][1],
                        bF[nh * 2 + 1][0], bF[nh * 2 + 1][1], addr);
            }
#pragma unroll
            for (int mi = 0; mi < 4; mi++)
#pragma unroll
                for (int ni = 0; ni < 4; ni++)
                    mma_f16(acc[mi][ni], aF[mi], bF[ni]);
        }
        __syncthreads();
    }

    // ---- epilogue (linear C, fp32) ----
    const bool doScale = IS_QKV && (n0 < 384);     // q columns
    const float qsc = doScale ? 0.17677669529663687f : 1.0f;
#pragma unroll
    for (int mi = 0; mi < 4; mi++) {
        int r0r = warpM * 64 + mi * 16 + grp;
#pragma unroll
        for (int half = 0; half < 2; half++) {
            int r = r0r + half * 8;
#pragma unroll
            for (int ni = 0; ni < 4; ni++) {
                int cc = warpN * 32 + ni * 8 + qk * 2;
                float c0 = acc[mi][ni][half * 2 + 0];
                float c1 = acc[mi][ni][half * 2 + 1];
                float* p = C + (size_t)(m0 + r) * cStride + n0 + cc;
                if (IS_QKV) {
                    *(float2*)p = make_float2(c0 * qsc, c1 * qsc);
                } else {
                    *(float2*)p = make_float2(c0 + g_bc[n0 + cc],
                                              c1 + g_bc[n0 + cc + 1]);
                }
            }
        }
    }
}

// ---------------- fp32 -> fp16 bulk convert ----------------
__global__ void f32to16(const float* __restrict__ src, __half* __restrict__ dst,
                        int n4)
{
    int i = blockIdx.x * blockDim.x + threadIdx.x;
    if (i < n4) {
        float4 v = *(const float4*)(src + (size_t)i * 4);
        uint2 o;
        o.x = f2h2(v.x, v.y);
        o.y = f2h2(v.z, v.w);
        *(uint2*)(dst + (size_t)i * 4) = o;
    }
}

// ---------------- weight transpose: Bt[n][k] = half(W[k][n]) ---------------
__global__ void transposeB(const float* __restrict__ W, __half* __restrict__ Bt,
                           int K, int N)
{
    __shared__ float t[32][33];
    int k0 = blockIdx.y * 32, n0 = blockIdx.x * 32;
    int x = threadIdx.x, y = threadIdx.y;
#pragma unroll
    for (int i = 0; i < 32; i += 8)
        t[y + i][x] = W[(size_t)(k0 + y + i) * N + n0 + x];
    __syncthreads();
#pragma unroll
    for (int i = 0; i < 32; i += 8)
        Bt[(size_t)(n0 + y + i) * K + k0 + x] = __float2half_rn(t[x][y + i]);
}

// ---------------- COMB: g_WcTh = half((wout @ wpost)^T)  (SIMT tf32) -------
__device__ __forceinline__ void mma_tf32(float* c, const float* a, const float* b) {
    asm volatile(
        "mma.sync.aligned.m16n8k8.row.col.f32.tf32.tf32.f32 "
        "{%0,%1,%2,%3}, {%4,%5,%6,%7}, {%8,%9}, {%0,%1,%2,%3};\n"
        : "+f"(c[0]), "+f"(c[1]), "+f"(c[2]), "+f"(c[3])
        : "r"(__float_as_uint(a[0])), "r"(__float_as_uint(a[1])),
          "r"(__float_as_uint(a[2])), "r"(__float_as_uint(a[3])),
          "r"(__float_as_uint(b[0])), "r"(__float_as_uint(b[1])));
}

__global__ __launch_bounds__(256)
void comb_gemm(const float* __restrict__ A, const float* __restrict__ B)
{
    __shared__ __align__(16) float As[2][128][20];
    __shared__ __align__(16) float Bs[2][16][136];
    const int tid = threadIdx.x;
    const int m0 = blockIdx.y * 128, n0 = blockIdx.x * 128;
    const int N = 384;

    const int aRow = tid >> 1, aCol = (tid & 1) * 8;
    const int bRow = tid >> 4, bCol = (tid & 15) * 8;
    const int lane = tid & 31, grp = lane >> 2, qk = lane & 3;
    const int warpId = tid >> 5;
    const int warpM = warpId & 1, warpN = warpId >> 1;

    const float* aPtr = A + (size_t)(m0 + aRow) * 384 + aCol;
    const float* bPtr = B + (size_t)bRow * N + n0 + bCol;

    float acc[4][4][4];
#pragma unroll
    for (int i = 0; i < 4; i++)
#pragma unroll
        for (int j = 0; j < 4; j++)
#pragma unroll
            for (int r = 0; r < 4; r++) acc[i][j][r] = 0.f;

    float4 ra0 = *(const float4*)(aPtr);
    float4 ra1 = *(const float4*)(aPtr + 4);
    float4 rb0 = *(const float4*)(bPtr);
    float4 rb1 = *(const float4*)(bPtr + 4);
    {
        float* d = &As[0][aRow][aCol];
        d[0]=f2tf(ra0.x); d[1]=f2tf(ra0.y); d[2]=f2tf(ra0.z); d[3]=f2tf(ra0.w);
        d[4]=f2tf(ra1.x); d[5]=f2tf(ra1.y); d[6]=f2tf(ra1.z); d[7]=f2tf(ra1.w);
        float* e = &Bs[0][bRow][bCol];
        e[0]=f2tf(rb0.x); e[1]=f2tf(rb0.y); e[2]=f2tf(rb0.z); e[3]=f2tf(rb0.w);
        e[4]=f2tf(rb1.x); e[5]=f2tf(rb1.y); e[6]=f2tf(rb1.z); e[7]=f2tf(rb1.w);
    }
    __syncthreads();

    const int NK = 24;
    int buf = 0;
    for (int kc = 0; kc < NK; kc++) {
        if (kc + 1 < NK) {
            const float* ap = aPtr + (kc + 1) * 16;
            const float* bp = bPtr + (size_t)(kc + 1) * 16 * N;
            ra0 = *(const float4*)(ap);
            ra1 = *(const float4*)(ap + 4);
            rb0 = *(const float4*)(bp);
            rb1 = *(const float4*)(bp + 4);
        }
#pragma unroll
        for (int s = 0; s < 16; s += 8) {
            float af[4][4], bf[4][2];
#pragma unroll
            for (int mi = 0; mi < 4; mi++) {
                int r = warpM * 64 + mi * 16 + grp;
                af[mi][0] = As[buf][r][s + qk];
                af[mi][1] = As[buf][r + 8][s + qk];
                af[mi][2] = As[buf][r][s + qk + 4];
                af[mi][3] = As[buf][r + 8][s + qk + 4];
            }
#pragma unroll
            for (int ni = 0; ni < 4; ni++) {
                int c = warpN * 32 + ni * 8 + grp;
                bf[ni][0] = Bs[buf][s + qk][c];
                bf[ni][1] = Bs[buf][s + qk + 4][c];
            }
#pragma unroll
            for (int mi = 0; mi < 4; mi++)
#pragma unroll
                for (int ni = 0; ni < 4; ni++)
                    mma_tf32(acc[mi][ni], af[mi], bf[ni]);
        }
        if (kc + 1 < NK) {
            int nb2 = buf ^ 1;
            float* d = &As[nb2][aRow][aCol];
            d[0]=f2tf(ra0.x); d[1]=f2tf(ra0.y); d[2]=f2tf(ra0.z); d[3]=f2tf(ra0.w);
            d[4]=f2tf(ra1.x); d[5]=f2tf(ra1.y); d[6]=f2tf(ra1.z); d[7]=f2tf(ra1.w);
            float* e = &Bs[nb2][bRow][bCol];
            e[0]=f2tf(rb0.x); e[1]=f2tf(rb0.y); e[2]=f2tf(rb0.z); e[3]=f2tf(rb0.w);
            e[4]=f2tf(rb1.x); e[5]=f2tf(rb1.y); e[6]=f2tf(rb1.z); e[7]=f2tf(rb1.w);
        }
        __syncthreads();
        buf ^= 1;
    }
    // transposed half store: g_WcTh[n][m]
#pragma unroll
    for (int mi = 0; mi < 4; mi++) {
        int r0r = warpM * 64 + mi * 16 + grp;
#pragma unroll
        for (int half = 0; half < 2; half++) {
            int gm = m0 + r0r + half * 8;
#pragma unroll
            for (int ni = 0; ni < 4; ni++) {
                int cc = n0 + warpN * 32 + ni * 8 + qk * 2;
                g_WcTh[(size_t)cc * 384 + gm]       = __float2half_rn(acc[mi][ni][half * 2 + 0]);
                g_WcTh[(size_t)(cc + 1) * 384 + gm] = __float2half_rn(acc[mi][ni][half * 2 + 1]);
            }
        }
    }
}

__global__ void bias_comb_kernel(const float* __restrict__ b_out,
                                 const float* __restrict__ w_post,
                                 const float* __restrict__ b_post)
{
    int j = blockIdx.x * blockDim.x + threadIdx.x;
    if (j < 384) {
        float s = b_post[j];
        for (int k = 0; k < 384; k++) s += b_out[k] * w_post[k * 384 + j];
        g_bc[j] = s;
    }
}

// ---------------- attention (row-batched per warp, roll folded in gather) --
__global__ __launch_bounds__(256)
void attn_kernel(const float* __restrict__ pe)
{
    __shared__ __align__(16) float qs[49 * 36];
    __shared__ __align__(16) float ks[49 * 36];
    __shared__ __align__(16) float vs[49 * 36];
    __shared__ __align__(16) float ps[49 * 52];
    __shared__ float pes[169];
    __shared__ int   tok[49];

    const int tid = threadIdx.x;
    const int bw  = blockIdx.x;
    const int win = bw & 63;
    const int bh  = bw >> 6;
    const int h   = bh % 12;
    const int b   = bh / 12;
    const int wy = win >> 3, wx = win & 7;

    if (tid < 49) {
        int xi = tid / 7, yi = tid - xi * 7;
        int oh = wy * 7 + xi + 3; if (oh >= 56) oh -= 56;   // roll fold
        int ow = wx * 7 + yi + 3; if (ow >= 56) ow -= 56;
        tok[tid] = (b * 56 + oh) * 56 + ow;
    }
    if (tid < 169) pes[tid] = pe[tid];
    __syncthreads();

    for (int i4 = tid; i4 < 392; i4 += 256) {
        int r = i4 >> 3;
        int c = (i4 & 7) * 4;
        const float* src = g_qkv + (size_t)tok[r] * 1152 + h * 32 + c;
        int o = r * 36 + c;
        *(float4*)(qs + o) = *(const float4*)(src);
        *(float4*)(ks + o) = *(const float4*)(src + 384);
        *(float4*)(vs + o) = *(const float4*)(src + 768);
    }
    __syncthreads();

    const bool mUL = (win >= 56);
    const bool mLR = ((win & 7) == 7);
    const int warp = tid >> 5, lane = tid & 31;
    const int j0 = lane;
    const int j1 = lane + 32;
    const bool j1v = (j1 < 49);
    const int j1c = j1v ? j1 : 48;
    const int xj0 = j0 / 7,  yj0 = j0  - xj0 * 7;
    const int xj1 = j1c / 7, yj1 = j1c - xj1 * 7;

    const int NR = (warp == 0) ? 7 : 6;

    float S0[7], S1[7];
#pragma unroll
    for (int rr = 0; rr < 7; rr++) { S0[rr] = 0.f; S1[rr] = 0.f; }

    const float4* ka4 = (const float4*)(ks + j0  * 36);
    const float4* kb4 = (const float4*)(ks + j1c * 36);
#pragma unroll
    for (int d4 = 0; d4 < 8; d4++) {
        float4 A = ka4[d4], Bv = kb4[d4];
#pragma unroll
        for (int rr = 0; rr < 7; rr++) {
            int i = warp + rr * 8;
            if (rr < NR) {
                float4 q = *(const float4*)(qs + i * 36 + d4 * 4);
                S0[rr] += q.x * A.x  + q.y * A.y  + q.z * A.z  + q.w * A.w;
                S1[rr] += q.x * Bv.x + q.y * Bv.y + q.z * Bv.z + q.w * Bv.w;
            }
        }
    }

#pragma unroll
    for (int rr = 0; rr < 7; rr++) {
        if (rr >= NR) break;
        const int i = warp + rr * 8;
        const int xi = i / 7, yi = i - xi * 7;
        float s0 = S0[rr] + pes[(xj0 - xi + 6) * 13 + (yj0 - yi + 6)];
        float s1 = S1[rr] + pes[(xj1 - xi + 6) * 13 + (yj1 - yi + 6)];
        if (mUL) {
            if ((i >= 28) != (j0  >= 28)) s0 = -1e30f;
            if ((i >= 28) != (j1c >= 28)) s1 = -1e30f;
        }
        if (mLR) {
            if ((yi >= 4) != (yj0 >= 4)) s0 = -1e30f;
            if ((yi >= 4) != (yj1 >= 4)) s1 = -1e30f;
        }
        if (!j1v) s1 = -1e30f;

        float mx = fmaxf(s0, s1);
#pragma unroll
        for (int o = 16; o > 0; o >>= 1)
            mx = fmaxf(mx, __shfl_xor_sync(0xffffffffu, mx, o));
        float e0 = __expf(s0 - mx);
        float e1 = j1v ? __expf(s1 - mx) : 0.f;
        float sum = e0 + e1;
#pragma unroll
        for (int o = 16; o > 0; o >>= 1)
            sum += __shfl_xor_sync(0xffffffffu, sum, o);
        float inv = 1.0f / sum;
        ps[i * 52 + j0] = e0 * inv;
        if (j1v) ps[i * 52 + j1] = e1 * inv;
    }
    __syncwarp();

    float acc[7];
#pragma unroll
    for (int rr = 0; rr < 7; rr++) acc[rr] = 0.f;

#pragma unroll
    for (int j4 = 0; j4 < 12; j4++) {
        float v0 = vs[(j4 * 4 + 0) * 36 + lane];
        float v1 = vs[(j4 * 4 + 1) * 36 + lane];
        float v2 = vs[(j4 * 4 + 2) * 36 + lane];
        float v3 = vs[(j4 * 4 + 3) * 36 + lane];
#pragma unroll
        for (int rr = 0; rr < 7; rr++) {
            if (rr < NR) {
                int i = warp + rr * 8;
                float4 p = *(const float4*)(ps + i * 52 + j4 * 4);
                acc[rr] += p.x * v0 + p.y * v1 + p.z * v2 + p.w * v3;
            }
        }
    }
    {
        float v48 = vs[48 * 36 + lane];
#pragma unroll
        for (int rr = 0; rr < 7; rr++)
            if (rr < NR) acc[rr] += ps[(warp + rr * 8) * 52 + 48] * v48;
    }

#pragma unroll
    for (int rr = 0; rr < 7; rr++) {
        if (rr >= NR) break;
        const int i = warp + rr * 8;
        g_attnh[(size_t)tok[i] * 384 + h * 32 + lane] = __float2half_rn(acc[rr]);
    }
}

extern "C" void kernel_launch(void* const* d_in, const int* in_sizes, int n_in,
                              void* d_out, int out_size)
{
    const float* x     = (const float*)d_in[0];
    const float* wqkv  = (const float*)d_in[1];
    const float* pe    = (const float*)d_in[2];
    const float* wout  = (const float*)d_in[3];
    const float* bout  = (const float*)d_in[4];
    const float* wpost = (const float*)d_in[5];
    const float* bpost = (const float*)d_in[6];
    float* out = (float*)d_out;

    (void)in_sizes; (void)n_in; (void)out_size;

    __half* g_xh_p;    cudaGetSymbolAddress((void**)&g_xh_p, g_xh);
    __half* g_attnh_p; cudaGetSymbolAddress((void**)&g_attnh_p, g_attnh);
    __half* g_BtQh_p;  cudaGetSymbolAddress((void**)&g_BtQh_p, g_BtQh);
    __half* g_WcTh_p;  cudaGetSymbolAddress((void**)&g_WcTh_p, g_WcTh);
    float*  g_qkv_p;   cudaGetSymbolAddress((void**)&g_qkv_p, g_qkv);

    const int n4 = M_TOK * 384 / 4;                       // 4,816,896
    f32to16<<<(n4 + 255) / 256, 256>>>(x, g_xh_p, n4);
    transposeB<<<dim3(36, 12), dim3(32, 8)>>>(wqkv, g_BtQh_p, 384, 1152);
    comb_gemm<<<dim3(3, 3), 256>>>(wout, wpost);
    bias_comb_kernel<<<2, 192>>>(bout, wpost, bpost);

    // qkv = xh @ w_qkv (linear), q scaled
    h16gemm<1><<<dim3(9, 392), 256>>>(g_xh_p, g_BtQh_p, g_qkv_p, 1152);

    attn_kernel<<<16 * 12 * 64, 256>>>(pe);

    // out = attnh @ Wc + bc (linear)
    h16gemm<0><<<dim3(3, 392), 256>>>(g_attnh_p, g_WcTh_p, out, 384);
}